// round 1
// baseline (speedup 1.0000x reference)
#include <cuda_runtime.h>
#include <math.h>

#define B_   256
#define D_   256
#define H_   8
#define HD_  32
#define FF_  1024
#define M_   2048
#define SCALE_ 0.17677669529663687f   /* 1/sqrt(32) */
#define THR_ 0.5f
#define MOM_ 0.9f
#define LR_  0.1f

// ---------------- scratch (device globals; no allocations allowed) ----------
__device__ float g_proj_src[B_ * 3 * D_];   // [B, 768]  q|k|v of src
__device__ float g_kv_mem[M_ * 2 * D_];     // [M, 512]  k|v of memory
__device__ float g_src_norm[B_];
__device__ float g_mem_norm[M_];
__device__ int   g_mem_nonzero;
__device__ int   g_max_bits[B_];            // ordered-int encoded max cosine sim
__device__ float g_ctx[B_ * D_];
__device__ float g_attn_tmp[B_ * D_];
__device__ float g_h[B_ * D_];
__device__ float g_hidden[B_ * FF_];
__device__ float g_ff[B_ * D_];

// monotone float<->int mapping for atomicMax on possibly-negative floats
__device__ __forceinline__ int   fenc(float f) { int i = __float_as_int(f); return i >= 0 ? i : (i ^ 0x7FFFFFFF); }
__device__ __forceinline__ float fdec(int i)   { return __int_as_float(i >= 0 ? i : (i ^ 0x7FFFFFFF)); }

// ---------------- init ------------------------------------------------------
__global__ void init_kernel() {
    int i = blockIdx.x * blockDim.x + threadIdx.x;
    if (i < B_) g_max_bits[i] = (int)0x807FFFFF;  // fenc(-inf)
    if (i == 0) g_mem_nonzero = 0;
}

// ---------------- row norms (src + memory) ----------------------------------
__global__ void norms_kernel(const float* __restrict__ src, const float* __restrict__ mem) {
    int row = blockIdx.x * 8 + threadIdx.y;
    int lane = threadIdx.x;
    if (row >= B_ + M_) return;
    bool is_src = row < B_;
    const float* base = is_src ? (src + row * D_) : (mem + (row - B_) * D_);
    float s = 0.f;
    #pragma unroll
    for (int d = lane; d < D_; d += 32) { float v = base[d]; s += v * v; }
    #pragma unroll
    for (int o = 16; o; o >>= 1) s += __shfl_xor_sync(0xFFFFFFFFu, s, o);
    if (lane == 0) {
        float nv = fmaxf(sqrtf(s), 1e-8f);
        if (is_src) g_src_norm[row] = nv;
        else {
            g_mem_norm[row - B_] = nv;
            if (s > 0.f) atomicOr(&g_mem_nonzero, 1);
        }
    }
}

// ---------------- generic tiled SGEMM: C[Mr,N] = A[Mr,K] @ B[N,K]^T ----------
// MODE 0: +bias store. MODE 1: cosine-sim max epilogue (no store). MODE 2: relu(+bias) store.
template <int MODE>
__global__ void sgemm_kernel(const float* __restrict__ A, const float* __restrict__ Bm,
                             const float* __restrict__ bias, float* __restrict__ C,
                             int Mr, int N, int K) {
    __shared__ float As[16][64];
    __shared__ float Bs[16][64];
    __shared__ int rowmax_s[64];

    int tid = threadIdx.x;
    int tx = tid & 15, ty = tid >> 4;
    int bm = blockIdx.y, bn = blockIdx.x;
    if (MODE == 1 && tid < 64) rowmax_s[tid] = (int)0x807FFFFF;

    float acc[4][4] = {};
    int ar = tid >> 2;           // 0..63
    int ac4 = (tid & 3) * 4;     // 0,4,8,12
    const float* Ap = A + (size_t)(bm * 64 + ar) * K + ac4;
    const float* Bp = Bm + (size_t)(bn * 64 + ar) * K + ac4;

    for (int k0 = 0; k0 < K; k0 += 16) {
        float4 a4 = *(const float4*)(Ap + k0);
        float4 b4 = *(const float4*)(Bp + k0);
        __syncthreads();
        As[ac4 + 0][ar] = a4.x; As[ac4 + 1][ar] = a4.y; As[ac4 + 2][ar] = a4.z; As[ac4 + 3][ar] = a4.w;
        Bs[ac4 + 0][ar] = b4.x; Bs[ac4 + 1][ar] = b4.y; Bs[ac4 + 2][ar] = b4.z; Bs[ac4 + 3][ar] = b4.w;
        __syncthreads();
        #pragma unroll
        for (int kk = 0; kk < 16; kk++) {
            float4 av = *(const float4*)&As[kk][ty * 4];
            float4 bv = *(const float4*)&Bs[kk][tx * 4];
            float a[4] = {av.x, av.y, av.z, av.w};
            float b[4] = {bv.x, bv.y, bv.z, bv.w};
            #pragma unroll
            for (int i = 0; i < 4; i++)
                #pragma unroll
                for (int j = 0; j < 4; j++) acc[i][j] += a[i] * b[j];
        }
    }

    int row0 = bm * 64 + ty * 4, col0 = bn * 64 + tx * 4;
    if (MODE == 1) {
        #pragma unroll
        for (int i = 0; i < 4; i++) {
            float inb = 1.f / g_src_norm[row0 + i];
            float mx = -1e30f;
            #pragma unroll
            for (int j = 0; j < 4; j++) {
                float v = acc[i][j] * inb / g_mem_norm[col0 + j];
                mx = fmaxf(mx, v);
            }
            atomicMax(&rowmax_s[ty * 4 + i], fenc(mx));
        }
        __syncthreads();
        if (tid < 64) atomicMax(&g_max_bits[bm * 64 + tid], rowmax_s[tid]);
    } else {
        #pragma unroll
        for (int i = 0; i < 4; i++)
            #pragma unroll
            for (int j = 0; j < 4; j++) {
                float v = acc[i][j] + (bias ? bias[col0 + j] : 0.f);
                if (MODE == 2) v = fmaxf(v, 0.f);
                C[(size_t)(row0 + i) * N + col0 + j] = v;
            }
    }
}

// ---------------- fused flash attention over memory + self token ------------
// grid (B/8, H); block 256 threads; warp w handles row b = bx*8+w, head = by.
__global__ void attn_kernel(const float* __restrict__ projsrc, const float* __restrict__ kv,
                            float* __restrict__ ctx) {
    __shared__ float q_s[8 * 33];
    __shared__ float vs_s[8 * 33];
    __shared__ float k_s[64 * 33];
    __shared__ float v_s[64 * 33];
    __shared__ float p_s[8 * 64];

    int h = blockIdx.y;
    int tid = threadIdx.x;
    int w = tid >> 5, lane = tid & 31;
    int b = blockIdx.x * 8 + w;

    float qv = projsrc[b * 768 + h * 32 + lane];
    q_s[w * 33 + lane] = qv;
    float kself = projsrc[b * 768 + 256 + h * 32 + lane];
    vs_s[w * 33 + lane] = projsrc[b * 768 + 512 + h * 32 + lane];
    float ls = qv * kself;
    #pragma unroll
    for (int o = 16; o; o >>= 1) ls += __shfl_xor_sync(0xFFFFFFFFu, ls, o);
    ls *= SCALE_;

    float ctxd = 0.f, rmax = -1e30f, lsum = 0.f;

    for (int m0 = 0; m0 < M_; m0 += 64) {
        __syncthreads();
        #pragma unroll
        for (int i = tid; i < 64 * 64; i += 256) {
            int r = i >> 6, c = i & 63;
            if (c < 32) k_s[r * 33 + c] = kv[(size_t)(m0 + r) * 512 + h * 32 + c];
            else        v_s[r * 33 + (c - 32)] = kv[(size_t)(m0 + r) * 512 + 256 + h * 32 + (c - 32)];
        }
        __syncthreads();
        #pragma unroll
        for (int g = 0; g < 2; g++) {
            int j = g * 32 + lane;
            float lg = 0.f;
            #pragma unroll
            for (int d = 0; d < 32; d++) lg += q_s[w * 33 + d] * k_s[j * 33 + d];
            lg *= SCALE_;
            float gm = lg;
            #pragma unroll
            for (int o = 16; o; o >>= 1) gm = fmaxf(gm, __shfl_xor_sync(0xFFFFFFFFu, gm, o));
            if (gm > rmax) {
                float f = __expf(rmax - gm);
                ctxd *= f; lsum *= f; rmax = gm;
            }
            float p = __expf(lg - rmax);
            lsum += p;
            p_s[w * 64 + j] = p;
            __syncwarp();
            #pragma unroll
            for (int jj = 0; jj < 32; jj++)
                ctxd += p_s[w * 64 + g * 32 + jj] * v_s[(g * 32 + jj) * 33 + lane];
            __syncwarp();
        }
    }
    // fold in self token, normalize
    float nmax = fmaxf(rmax, ls);
    float f = __expf(rmax - nmax);
    ctxd *= f; lsum *= f;
    float ps = __expf(ls - nmax);
    float tot = lsum;
    #pragma unroll
    for (int o = 16; o; o >>= 1) tot += __shfl_xor_sync(0xFFFFFFFFu, tot, o);
    tot += ps;
    ctxd = (ctxd + ps * vs_s[w * 33 + lane]) / tot;
    ctx[b * D_ + h * 32 + lane] = ctxd;
}

// ---------------- LayerNorm: out = LN(a+b)*g + be ---------------------------
__global__ void ln_kernel(const float* __restrict__ a, const float* __restrict__ bb,
                          const float* __restrict__ g, const float* __restrict__ be,
                          float* __restrict__ out) {
    __shared__ float red[256];
    __shared__ float s_mean, s_rstd;
    int row = blockIdx.x, d = threadIdx.x;
    float x = a[row * D_ + d] + bb[row * D_ + d];
    red[d] = x; __syncthreads();
    #pragma unroll
    for (int o = 128; o; o >>= 1) { if (d < o) red[d] += red[d + o]; __syncthreads(); }
    if (d == 0) s_mean = red[0] * (1.f / D_);
    __syncthreads();
    float c = x - s_mean;
    red[d] = c * c; __syncthreads();
    #pragma unroll
    for (int o = 128; o; o >>= 1) { if (d < o) red[d] += red[d + o]; __syncthreads(); }
    if (d == 0) s_rstd = rsqrtf(red[0] * (1.f / D_) + 1e-5f);
    __syncthreads();
    out[row * D_ + d] = c * s_rstd * g[d] + be[d];
}

// ---------------- memory scatter update (parallelized scan) -----------------
// cond_i = (s_i > THR) || (i < M - ptr); idx = (ptr + rank_i) mod M; indices distinct.
__global__ void scatter_kernel(const float* __restrict__ mem, const float* __restrict__ mom,
                               float* __restrict__ out_mem, float* __restrict__ out_mom,
                               float* __restrict__ out_sc, const int* __restrict__ ptrp) {
    __shared__ int conds[256];
    __shared__ int pref[256];
    __shared__ float svals[256];
    int t = threadIdx.x;
    int flag = g_mem_nonzero;
    float s = flag ? (1.0f - fdec(g_max_bits[t])) : 1.0f;
    int ptr = *ptrp;
    long long forced = (long long)M_ - (long long)ptr;
    int cond = (s > THR_) || ((long long)t < forced);
    svals[t] = s; conds[t] = cond;
    __syncthreads();
    if (t == 0) {
        int r = 0;
        for (int i = 0; i < 256; i++) { pref[i] = r; r += conds[i]; }
    }
    __syncthreads();
    for (int i = 0; i < 256; i++) {
        if (!conds[i]) continue;
        long long p = (long long)ptr + pref[i];
        int idx = (int)(p % M_); if (idx < 0) idx += M_;
        float mval = mem[(size_t)idx * D_ + t];
        float diff = g_h[i * D_ + t] - mval;
        float nm = MOM_ * mom[(size_t)idx * D_ + t] + (1.0f - MOM_) * diff;
        out_mem[(size_t)idx * D_ + t] = mval + LR_ * nm;
        out_mom[(size_t)idx * D_ + t] = nm;
        if (t == 0) out_sc[idx] = svals[i];
    }
}

// ---------------- launch ----------------------------------------------------
extern "C" void kernel_launch(void* const* d_in, const int* in_sizes, int n_in,
                              void* d_out, int out_size) {
    const float* src       = (const float*)d_in[0];
    const float* memory    = (const float*)d_in[1];
    const float* momentum  = (const float*)d_in[2];
    const float* scores    = (const float*)d_in[3];
    const float* in_proj_w = (const float*)d_in[4];
    const float* in_proj_b = (const float*)d_in[5];
    const float* out_w     = (const float*)d_in[6];
    const float* out_b     = (const float*)d_in[7];
    const float* w1        = (const float*)d_in[8];
    const float* b1        = (const float*)d_in[9];
    const float* w2        = (const float*)d_in[10];
    const float* b2        = (const float*)d_in[11];
    const float* g1        = (const float*)d_in[12];
    const float* be1       = (const float*)d_in[13];
    const float* g2        = (const float*)d_in[14];
    const float* be2       = (const float*)d_in[15];
    const int*   ptr       = (const int*)d_in[16];

    float* out     = (float*)d_out;
    float* out_mem = out + B_ * D_;
    float* out_mom = out_mem + M_ * D_;
    float* out_sc  = out_mom + M_ * D_;

    float *proj_src_p, *kv_p, *ctx_p, *attn_p, *h_p, *hid_p, *ff_p;
    cudaGetSymbolAddress((void**)&proj_src_p, g_proj_src);
    cudaGetSymbolAddress((void**)&kv_p,  g_kv_mem);
    cudaGetSymbolAddress((void**)&ctx_p, g_ctx);
    cudaGetSymbolAddress((void**)&attn_p, g_attn_tmp);
    cudaGetSymbolAddress((void**)&h_p,   g_h);
    cudaGetSymbolAddress((void**)&hid_p, g_hidden);
    cudaGetSymbolAddress((void**)&ff_p,  g_ff);

    init_kernel<<<1, 256>>>();
    norms_kernel<<<(B_ + M_ + 7) / 8, dim3(32, 8)>>>(src, memory);

    // src projections: [256,768] = src @ in_proj_w^T + in_proj_b
    sgemm_kernel<0><<<dim3(768 / 64, 256 / 64), 256>>>(src, in_proj_w, in_proj_b, proj_src_p, 256, 768, 256);
    // memory k/v: [2048,512] = memory @ in_proj_w[D:3D]^T + in_proj_b[D:3D]
    sgemm_kernel<0><<<dim3(512 / 64, 2048 / 64), 256>>>(memory, in_proj_w + D_ * D_, in_proj_b + D_, kv_p, 2048, 512, 256);
    // cosine-sim max (surprise): src @ memory^T with norm epilogue + atomicMax
    sgemm_kernel<1><<<dim3(2048 / 64, 256 / 64), 256>>>(src, memory, nullptr, nullptr, 256, 2048, 256);

    // fused attention -> ctx
    attn_kernel<<<dim3(B_ / 8, H_), 256>>>(proj_src_p, kv_p, ctx_p);

    // attn_out = ctx @ out_w^T + out_b;  h = LN(src + attn_out)
    sgemm_kernel<0><<<dim3(256 / 64, 256 / 64), 256>>>(ctx_p, out_w, out_b, attn_p, 256, 256, 256);
    ln_kernel<<<B_, 256>>>(src, attn_p, g1, be1, h_p);

    // memory update outputs: copy-then-scatter
    cudaMemcpyAsync(out_mem, memory,   (size_t)M_ * D_ * sizeof(float), cudaMemcpyDeviceToDevice, 0);
    cudaMemcpyAsync(out_mom, momentum, (size_t)M_ * D_ * sizeof(float), cudaMemcpyDeviceToDevice, 0);
    cudaMemcpyAsync(out_sc,  scores,   (size_t)M_ * sizeof(float),      cudaMemcpyDeviceToDevice, 0);
    scatter_kernel<<<1, 256>>>(memory, momentum, out_mem, out_mom, out_sc, ptr);

    // FFN: relu(h @ w1^T + b1) @ w2^T + b2;  out = LN(h + ff)
    sgemm_kernel<2><<<dim3(1024 / 64, 256 / 64), 256>>>(h_p, w1, b1, hid_p, 256, 1024, 256);
    sgemm_kernel<0><<<dim3(256 / 64, 256 / 64), 256>>>(hid_p, w2, b2, ff_p, 256, 256, 1024);
    ln_kernel<<<B_, 256>>>(h_p, ff_p, g2, be2, out);
}

// round 2
// speedup vs baseline: 1.2542x; 1.2542x over previous
#include <cuda_runtime.h>
#include <math.h>

#define B_   256
#define D_   256
#define H_   8
#define HD_  32
#define FF_  1024
#define M_   2048
#define SCALE_ 0.17677669529663687f   /* 1/sqrt(32) */
#define THR_ 0.5f
#define MOM_ 0.9f
#define LR_  0.1f
#define NSPLIT_ 8
#define KSPLIT_ (M_ / NSPLIT_)   /* 256 keys per split */

// ---------------- scratch (device globals; no allocations allowed) ----------
__device__ float g_proj_src[B_ * 3 * D_];      // [B,768] q|k|v of src
__device__ float g_kv_mem[M_ * 2 * D_];        // [M,512] k|v of memory
__device__ float g_logits[H_ * B_ * M_];       // [H][B][M] logits -> probs (16.8MB)
__device__ float g_pself[H_ * B_];             // normalized self prob
__device__ float g_ctx_part[NSPLIT_ * B_ * D_];// split-K partials (2MB)
__device__ float g_src_norm[B_];
__device__ float g_mem_norm[M_];
__device__ int   g_mem_nonzero;
__device__ int   g_max_bits[B_];               // ordered-int max cosine sim
__device__ float g_ctx[B_ * D_];
__device__ float g_attn_tmp[B_ * D_];
__device__ float g_h[B_ * D_];
__device__ float g_hidden[B_ * FF_];
__device__ float g_ff[B_ * D_];
__device__ int   g_upd_idx[B_];
__device__ float g_upd_s[B_];

__device__ __forceinline__ int   fenc(float f) { int i = __float_as_int(f); return i >= 0 ? i : (i ^ 0x7FFFFFFF); }
__device__ __forceinline__ float fdec(int i)   { return __int_as_float(i >= 0 ? i : (i ^ 0x7FFFFFFF)); }

// ---------------- init ------------------------------------------------------
__global__ void init_kernel() {
    int i = threadIdx.x;
    if (i < B_) g_max_bits[i] = (int)0x807FFFFF;  // fenc(-inf)
    if (i == 0) g_mem_nonzero = 0;
}

// ---------------- row norms (src + memory) ----------------------------------
__global__ void norms_kernel(const float* __restrict__ src, const float* __restrict__ mem) {
    int row = blockIdx.x * 8 + threadIdx.y;
    int lane = threadIdx.x;
    if (row >= B_ + M_) return;
    bool is_src = row < B_;
    const float* base = is_src ? (src + row * D_) : (mem + (row - B_) * D_);
    float s = 0.f;
    #pragma unroll
    for (int d = lane; d < D_; d += 32) { float v = base[d]; s += v * v; }
    #pragma unroll
    for (int o = 16; o; o >>= 1) s += __shfl_xor_sync(0xFFFFFFFFu, s, o);
    if (lane == 0) {
        float nv = fmaxf(sqrtf(s), 1e-8f);
        if (is_src) g_src_norm[row] = nv;
        else {
            g_mem_norm[row - B_] = nv;
            if (s > 0.f) atomicOr(&g_mem_nonzero, 1);
        }
    }
}

// ---------------- SGEMM: C[Mr,N] = A[Mr,K] @ B[N,K]^T  (64x64 tile, 64 thr, 8x8 micro)
// MODE 0: (+bias) store. MODE 1: cosine-sim max epilogue. MODE 2: relu(+bias) store.
// Batched over blockIdx.z via byte-free element strides aB,bB,cB.
template <int MODE>
__global__ void __launch_bounds__(64)
sgemm64(const float* __restrict__ A, const float* __restrict__ Bm,
        const float* __restrict__ bias, float* __restrict__ C,
        int K, int lda, int ldb, int ldc, int aB, int bB, int cB) {
    __shared__ float As[16][64];
    __shared__ float Bs[16][64];
    int tid = threadIdx.x;
    int tx = tid & 7, ty = tid >> 3;
    const float* Ap = A + (size_t)blockIdx.z * aB + (size_t)(blockIdx.y * 64 + tid) * lda;
    const float* Bp = Bm + (size_t)blockIdx.z * bB + (size_t)(blockIdx.x * 64 + tid) * ldb;

    float acc[8][8] = {};
    for (int k0 = 0; k0 < K; k0 += 16) {
        __syncthreads();
        #pragma unroll
        for (int s = 0; s < 4; s++) {
            float4 a4 = *(const float4*)(Ap + k0 + s * 4);
            float4 b4 = *(const float4*)(Bp + k0 + s * 4);
            As[s * 4 + 0][tid] = a4.x; As[s * 4 + 1][tid] = a4.y;
            As[s * 4 + 2][tid] = a4.z; As[s * 4 + 3][tid] = a4.w;
            Bs[s * 4 + 0][tid] = b4.x; Bs[s * 4 + 1][tid] = b4.y;
            Bs[s * 4 + 2][tid] = b4.z; Bs[s * 4 + 3][tid] = b4.w;
        }
        __syncthreads();
        #pragma unroll
        for (int kk = 0; kk < 16; kk++) {
            float a[8], b[8];
            *(float4*)&a[0] = *(const float4*)&As[kk][ty * 8];
            *(float4*)&a[4] = *(const float4*)&As[kk][ty * 8 + 4];
            *(float4*)&b[0] = *(const float4*)&Bs[kk][tx * 8];
            *(float4*)&b[4] = *(const float4*)&Bs[kk][tx * 8 + 4];
            #pragma unroll
            for (int i = 0; i < 8; i++)
                #pragma unroll
                for (int j = 0; j < 8; j++) acc[i][j] += a[i] * b[j];
        }
    }

    int row0 = blockIdx.y * 64 + ty * 8;
    int col0 = blockIdx.x * 64 + tx * 8;
    if (MODE == 1) {
        float inm[8];
        #pragma unroll
        for (int j = 0; j < 8; j++) inm[j] = 1.f / g_mem_norm[col0 + j];
        #pragma unroll
        for (int i = 0; i < 8; i++) {
            float ins = 1.f / g_src_norm[row0 + i];
            float mx = -1e30f;
            #pragma unroll
            for (int j = 0; j < 8; j++) mx = fmaxf(mx, acc[i][j] * ins * inm[j]);
            #pragma unroll
            for (int o = 4; o; o >>= 1) mx = fmaxf(mx, __shfl_xor_sync(0xFFFFFFFFu, mx, o));
            if (tx == 0) atomicMax(&g_max_bits[row0 + i], fenc(mx));
        }
    } else {
        float bj[8];
        #pragma unroll
        for (int j = 0; j < 8; j++) bj[j] = bias ? bias[col0 + j] : 0.f;
        float* Cb = C + (size_t)blockIdx.z * cB;
        #pragma unroll
        for (int i = 0; i < 8; i++) {
            float4 o0, o1;
            float v[8];
            #pragma unroll
            for (int j = 0; j < 8; j++) {
                v[j] = acc[i][j] + bj[j];
                if (MODE == 2) v[j] = fmaxf(v[j], 0.f);
            }
            o0 = make_float4(v[0], v[1], v[2], v[3]);
            o1 = make_float4(v[4], v[5], v[6], v[7]);
            *(float4*)&Cb[(size_t)(row0 + i) * ldc + col0] = o0;
            *(float4*)&Cb[(size_t)(row0 + i) * ldc + col0 + 4] = o1;
        }
    }
}

// ---------------- softmax over [M logits + self], normalized in place -------
// grid = H*B blocks, 256 threads; logits layout [h][b][m]
__global__ void softmax_kernel(float* __restrict__ logits, const float* __restrict__ projsrc,
                               float* __restrict__ pself) {
    int h = blockIdx.x >> 8, b = blockIdx.x & 255;
    int tid = threadIdx.x, w = tid >> 5, lane = tid & 31;
    float* row = logits + ((size_t)(h * B_ + b)) * M_;

    __shared__ float s_ls, smax[8], ssum[8];
    if (tid < 32) {
        float q = projsrc[b * 768 + h * 32 + tid];
        float k = projsrc[b * 768 + 256 + h * 32 + tid];
        float d = q * k;
        #pragma unroll
        for (int o = 16; o; o >>= 1) d += __shfl_xor_sync(0xFFFFFFFFu, d, o);
        if (tid == 0) s_ls = d * SCALE_;
    }
    float4 v0 = ((const float4*)row)[tid * 2];
    float4 v1 = ((const float4*)row)[tid * 2 + 1];
    float x[8] = {v0.x, v0.y, v0.z, v0.w, v1.x, v1.y, v1.z, v1.w};
    float lmax = -1e30f;
    #pragma unroll
    for (int j = 0; j < 8; j++) { x[j] *= SCALE_; lmax = fmaxf(lmax, x[j]); }
    #pragma unroll
    for (int o = 16; o; o >>= 1) lmax = fmaxf(lmax, __shfl_xor_sync(0xFFFFFFFFu, lmax, o));
    if (lane == 0) smax[w] = lmax;
    __syncthreads();
    float gmax = s_ls;
    #pragma unroll
    for (int i = 0; i < 8; i++) gmax = fmaxf(gmax, smax[i]);
    float lsum = 0.f;
    #pragma unroll
    for (int j = 0; j < 8; j++) { x[j] = __expf(x[j] - gmax); lsum += x[j]; }
    #pragma unroll
    for (int o = 16; o; o >>= 1) lsum += __shfl_xor_sync(0xFFFFFFFFu, lsum, o);
    if (lane == 0) ssum[w] = lsum;
    __syncthreads();
    float eself = __expf(s_ls - gmax);
    float tot = eself;
    #pragma unroll
    for (int i = 0; i < 8; i++) tot += ssum[i];
    float inv = 1.f / tot;
    #pragma unroll
    for (int j = 0; j < 8; j++) x[j] *= inv;
    ((float4*)row)[tid * 2]     = make_float4(x[0], x[1], x[2], x[3]);
    ((float4*)row)[tid * 2 + 1] = make_float4(x[4], x[5], x[6], x[7]);
    if (tid == 0) pself[h * B_ + b] = eself * inv;
}

// ---------------- AV split-K: partial[s][b][h*32+d] = P_h[b, ks] @ V_h[ks, d]
// grid (qb=4, split=8, h=8), 64 threads; tile 64 rows x 32 cols; micro 8x4.
__global__ void __launch_bounds__(64)
av_kernel(const float* __restrict__ probs, const float* __restrict__ kv,
          float* __restrict__ part) {
    __shared__ float Ps[16][64];
    __shared__ float Vs[16][32];
    int tid = threadIdx.x;
    int tx = tid & 7, ty = tid >> 3;
    int qb = blockIdx.x, split = blockIdx.y, h = blockIdx.z;

    const float* Prow = probs + ((size_t)(h * B_ + qb * 64 + tid)) * M_ + split * KSPLIT_;
    int vr = tid >> 2, vc = (tid & 3) * 8;

    float acc[8][4] = {};
    for (int k0 = 0; k0 < KSPLIT_; k0 += 16) {
        __syncthreads();
        #pragma unroll
        for (int s = 0; s < 4; s++) {
            float4 p4 = *(const float4*)(Prow + k0 + s * 4);
            Ps[s * 4 + 0][tid] = p4.x; Ps[s * 4 + 1][tid] = p4.y;
            Ps[s * 4 + 2][tid] = p4.z; Ps[s * 4 + 3][tid] = p4.w;
        }
        {
            const float* vp = kv + (size_t)(split * KSPLIT_ + k0 + vr) * 512 + 256 + h * 32 + vc;
            float4 va = *(const float4*)vp;
            float4 vb = *(const float4*)(vp + 4);
            *(float4*)&Vs[vr][vc] = va;
            *(float4*)&Vs[vr][vc + 4] = vb;
        }
        __syncthreads();
        #pragma unroll
        for (int kk = 0; kk < 16; kk++) {
            float a[8], b[4];
            *(float4*)&a[0] = *(const float4*)&Ps[kk][ty * 8];
            *(float4*)&a[4] = *(const float4*)&Ps[kk][ty * 8 + 4];
            *(float4*)&b[0] = *(const float4*)&Vs[kk][tx * 4];
            #pragma unroll
            for (int i = 0; i < 8; i++)
                #pragma unroll
                for (int j = 0; j < 4; j++) acc[i][j] += a[i] * b[j];
        }
    }
    #pragma unroll
    for (int i = 0; i < 8; i++) {
        float4 o = make_float4(acc[i][0], acc[i][1], acc[i][2], acc[i][3]);
        *(float4*)&part[(size_t)split * (B_ * D_) + (size_t)(qb * 64 + ty * 8 + i) * D_ + h * 32 + tx * 4] = o;
    }
}

// ---------------- reduce partials + self term -> ctx -------------------------
__global__ void reduce_ctx_kernel(const float* __restrict__ part, const float* __restrict__ pself,
                                  const float* __restrict__ projsrc, float* __restrict__ ctx) {
    int b = blockIdx.x, d = threadIdx.x;
    int h = d >> 5;
    float s = 0.f;
    #pragma unroll
    for (int sp = 0; sp < NSPLIT_; sp++) s += part[(size_t)sp * (B_ * D_) + b * D_ + d];
    s += pself[h * B_ + b] * projsrc[b * 768 + 512 + d];
    ctx[b * D_ + d] = s;
}

// ---------------- LayerNorm: out = LN(a+b)*g + be (warp per row) ------------
__global__ void ln_kernel(const float* __restrict__ a, const float* __restrict__ bb,
                          const float* __restrict__ g, const float* __restrict__ be,
                          float* __restrict__ out) {
    int w = threadIdx.x >> 5, lane = threadIdx.x & 31;
    int row = blockIdx.x * 8 + w;
    const float4* ap = (const float4*)(a + row * D_) + lane * 2;
    const float4* bp = (const float4*)(bb + row * D_) + lane * 2;
    float4 a0 = ap[0], a1 = ap[1], b0 = bp[0], b1 = bp[1];
    float x[8] = {a0.x + b0.x, a0.y + b0.y, a0.z + b0.z, a0.w + b0.w,
                  a1.x + b1.x, a1.y + b1.y, a1.z + b1.z, a1.w + b1.w};
    float s = 0.f;
    #pragma unroll
    for (int j = 0; j < 8; j++) s += x[j];
    #pragma unroll
    for (int o = 16; o; o >>= 1) s += __shfl_xor_sync(0xFFFFFFFFu, s, o);
    float mean = s * (1.f / D_);
    float v = 0.f;
    #pragma unroll
    for (int j = 0; j < 8; j++) { float c = x[j] - mean; v += c * c; }
    #pragma unroll
    for (int o = 16; o; o >>= 1) v += __shfl_xor_sync(0xFFFFFFFFu, v, o);
    float rstd = rsqrtf(v * (1.f / D_) + 1e-5f);
    const float4* gp = (const float4*)g + lane * 2;
    const float4* bep = (const float4*)be + lane * 2;
    float4 g0 = gp[0], g1 = gp[1], e0 = bep[0], e1 = bep[1];
    float gg[8] = {g0.x, g0.y, g0.z, g0.w, g1.x, g1.y, g1.z, g1.w};
    float ee[8] = {e0.x, e0.y, e0.z, e0.w, e1.x, e1.y, e1.z, e1.w};
    float o8[8];
    #pragma unroll
    for (int j = 0; j < 8; j++) o8[j] = (x[j] - mean) * rstd * gg[j] + ee[j];
    float4* op = (float4*)(out + row * D_) + lane * 2;
    op[0] = make_float4(o8[0], o8[1], o8[2], o8[3]);
    op[1] = make_float4(o8[4], o8[5], o8[6], o8[7]);
}

// ---------------- scatter: prep (prefix) + apply -----------------------------
__global__ void scatter_prep_kernel(const int* __restrict__ ptrp) {
    __shared__ int conds[256];
    __shared__ int pref[256];
    int t = threadIdx.x;
    int flag = g_mem_nonzero;
    float s = flag ? (1.0f - fdec(g_max_bits[t])) : 1.0f;
    int ptr = *ptrp;
    long long forced = (long long)M_ - (long long)ptr;
    int cond = (s > THR_) || ((long long)t < forced);
    conds[t] = cond;
    __syncthreads();
    if (t == 0) {
        int r = 0;
        for (int i = 0; i < 256; i++) { pref[i] = r; r += conds[i]; }
    }
    __syncthreads();
    int idx = -1;
    if (cond) {
        long long p = (long long)ptr + pref[t];
        idx = (int)(p % M_); if (idx < 0) idx += M_;
    }
    g_upd_idx[t] = idx;
    g_upd_s[t] = s;
}

__global__ void scatter_apply_kernel(const float* __restrict__ mem, const float* __restrict__ mom,
                                     float* __restrict__ out_mem, float* __restrict__ out_mom,
                                     float* __restrict__ out_sc) {
    int i = blockIdx.x;
    int idx = g_upd_idx[i];
    if (idx < 0) return;
    int t = threadIdx.x;
    float mval = mem[(size_t)idx * D_ + t];
    float diff = g_h[i * D_ + t] - mval;
    float nm = MOM_ * mom[(size_t)idx * D_ + t] + (1.0f - MOM_) * diff;
    out_mem[(size_t)idx * D_ + t] = mval + LR_ * nm;
    out_mom[(size_t)idx * D_ + t] = nm;
    if (t == 0) out_sc[idx] = g_upd_s[i];
}

// ---------------- launch ----------------------------------------------------
extern "C" void kernel_launch(void* const* d_in, const int* in_sizes, int n_in,
                              void* d_out, int out_size) {
    const float* src       = (const float*)d_in[0];
    const float* memory    = (const float*)d_in[1];
    const float* momentum  = (const float*)d_in[2];
    const float* scores    = (const float*)d_in[3];
    const float* in_proj_w = (const float*)d_in[4];
    const float* in_proj_b = (const float*)d_in[5];
    const float* out_w     = (const float*)d_in[6];
    const float* out_b     = (const float*)d_in[7];
    const float* w1        = (const float*)d_in[8];
    const float* b1        = (const float*)d_in[9];
    const float* w2        = (const float*)d_in[10];
    const float* b2        = (const float*)d_in[11];
    const float* g1        = (const float*)d_in[12];
    const float* be1       = (const float*)d_in[13];
    const float* g2        = (const float*)d_in[14];
    const float* be2       = (const float*)d_in[15];
    const int*   ptr       = (const int*)d_in[16];

    float* out     = (float*)d_out;
    float* out_mem = out + B_ * D_;
    float* out_mom = out_mem + M_ * D_;
    float* out_sc  = out_mom + M_ * D_;

    float *proj_p, *kv_p, *log_p, *pself_p, *part_p, *ctx_p, *attn_p, *h_p, *hid_p, *ff_p;
    cudaGetSymbolAddress((void**)&proj_p,  g_proj_src);
    cudaGetSymbolAddress((void**)&kv_p,    g_kv_mem);
    cudaGetSymbolAddress((void**)&log_p,   g_logits);
    cudaGetSymbolAddress((void**)&pself_p, g_pself);
    cudaGetSymbolAddress((void**)&part_p,  g_ctx_part);
    cudaGetSymbolAddress((void**)&ctx_p,   g_ctx);
    cudaGetSymbolAddress((void**)&attn_p,  g_attn_tmp);
    cudaGetSymbolAddress((void**)&h_p,     g_h);
    cudaGetSymbolAddress((void**)&hid_p,   g_hidden);
    cudaGetSymbolAddress((void**)&ff_p,    g_ff);

    init_kernel<<<1, 256>>>();
    norms_kernel<<<(B_ + M_ + 7) / 8, dim3(32, 8)>>>(src, memory);

    // src projections [256,768] = src @ in_proj_w^T + b
    sgemm64<0><<<dim3(768 / 64, 256 / 64, 1), 64>>>(src, in_proj_w, in_proj_b, proj_p,
                                                    256, 256, 256, 768, 0, 0, 0);
    // memory k|v [2048,512]
    sgemm64<0><<<dim3(512 / 64, 2048 / 64, 1), 64>>>(memory, in_proj_w + D_ * D_, in_proj_b + D_, kv_p,
                                                     256, 256, 256, 512, 0, 0, 0);
    // surprise: max cosine sim epilogue
    sgemm64<1><<<dim3(2048 / 64, 256 / 64, 1), 64>>>(src, memory, nullptr, nullptr,
                                                     256, 256, 256, 0, 0, 0, 0);
    // attention logits, batched per head: q_h[256,32] @ k_h[2048,32]^T
    sgemm64<0><<<dim3(2048 / 64, 256 / 64, H_), 64>>>(proj_p, kv_p, nullptr, log_p,
                                                      32, 768, 512, 2048, 32, 32, B_ * M_);
    // softmax (+self token), normalize probs in place
    softmax_kernel<<<H_ * B_, 256>>>(log_p, proj_p, pself_p);
    // AV split-K partials, then reduce (+self value term)
    av_kernel<<<dim3(B_ / 64, NSPLIT_, H_), 64>>>(log_p, kv_p, part_p);
    reduce_ctx_kernel<<<B_, 256>>>(part_p, pself_p, proj_p, ctx_p);

    // out projection + LN1
    sgemm64<0><<<dim3(256 / 64, 256 / 64, 1), 64>>>(ctx_p, out_w, out_b, attn_p,
                                                    256, 256, 256, 256, 0, 0, 0);
    ln_kernel<<<B_ / 8, 256>>>(src, attn_p, g1, be1, h_p);

    // memory update: copy originals, then scatter accepted rows
    cudaMemcpyAsync(out_mem, memory,   (size_t)M_ * D_ * sizeof(float), cudaMemcpyDeviceToDevice, 0);
    cudaMemcpyAsync(out_mom, momentum, (size_t)M_ * D_ * sizeof(float), cudaMemcpyDeviceToDevice, 0);
    cudaMemcpyAsync(out_sc,  scores,   (size_t)M_ * sizeof(float),      cudaMemcpyDeviceToDevice, 0);
    scatter_prep_kernel<<<1, 256>>>(ptr);
    scatter_apply_kernel<<<B_, 256>>>(memory, momentum, out_mem, out_mom, out_sc);

    // FFN + LN2
    sgemm64<2><<<dim3(1024 / 64, 256 / 64, 1), 64>>>(h_p, w1, b1, hid_p,
                                                     256, 256, 256, 1024, 0, 0, 0);
    sgemm64<0><<<dim3(256 / 64, 256 / 64, 1), 64>>>(hid_p, w2, b2, ff_p,
                                                    1024, 1024, 1024, 256, 0, 0, 0);
    ln_kernel<<<B_ / 8, 256>>>(h_p, ff_p, g2, be2, out);
}

// round 3
// speedup vs baseline: 2.4923x; 1.9872x over previous
#include <cuda_runtime.h>
#include <math.h>

#define B_   256
#define D_   256
#define H_   8
#define HD_  32
#define FF_  1024
#define M_   2048
#define SCALE_ 0.17677669529663687f   /* 1/sqrt(32) */
#define THR_ 0.5f
#define MOM_ 0.9f
#define LR_  0.1f
#define NSPLIT_ 8
#define KSPLIT_ (M_ / NSPLIT_)   /* 256 keys per split */

// ---------------- scratch (device globals) -----------------------------------
__device__ float g_proj_src[B_ * 3 * D_];        // [B,768] q|k|v of src
__device__ float g_kv_mem[M_ * 2 * D_];          // [M,512] k|v of memory
__device__ float g_logits[H_ * B_ * M_];         // [H][B][M] logits -> probs
__device__ float g_pself[H_ * B_];
__device__ float g_ctx_part[NSPLIT_ * B_ * D_];  // AV split-K partials
__device__ float g_attn_part[4 * B_ * D_];       // out-proj split-K partials
__device__ float g_ff_part[8 * B_ * D_];         // FFN2 split-K partials
__device__ float g_blockmax[32 * B_];            // cosine per-(bn,row) maxima
__device__ float g_src_norm[B_];
__device__ float g_mem_norm[M_];
__device__ float g_mem_sq[M_];
__device__ float g_ctx[B_ * D_];
__device__ float g_h[B_ * D_];
__device__ float g_hidden[B_ * FF_];
__device__ int   g_row_src[M_];                  // mem row -> update source (or -1)
__device__ float g_upd_s[B_];

// ---------------- row norms --------------------------------------------------
__global__ void norms_kernel(const float* __restrict__ src, const float* __restrict__ mem) {
    int row = blockIdx.x * 8 + threadIdx.y;
    int lane = threadIdx.x;
    if (row >= B_ + M_) return;
    bool is_src = row < B_;
    const float* base = is_src ? (src + row * D_) : (mem + (row - B_) * D_);
    float s = 0.f;
    #pragma unroll
    for (int d = lane; d < D_; d += 32) { float v = base[d]; s += v * v; }
    #pragma unroll
    for (int o = 16; o; o >>= 1) s += __shfl_xor_sync(0xFFFFFFFFu, s, o);
    if (lane == 0) {
        float nv = fmaxf(sqrtf(s), 1e-8f);
        if (is_src) g_src_norm[row] = nv;
        else { g_mem_norm[row - B_] = nv; g_mem_sq[row - B_] = s; }
    }
}

// ---------------- SGEMM: C[.,N] = A @ B^T, 64x64 tile, 128 thr, 8x4 micro ----
// Double-buffered smem, one __syncthreads per k-iter.
// MODE 0: (+bias) store. MODE 1: cosine blockmax epilogue. MODE 2: relu+bias.
// z-dim batching/split-K via element strides aB,bB,cB.
template <int MODE>
__global__ void __launch_bounds__(128)
sgemm128(const float* __restrict__ A, const float* __restrict__ Bm,
         const float* __restrict__ bias, float* __restrict__ C,
         int K, int lda, int ldb, int ldc, int aB, int bB, int cB) {
    __shared__ float As[2][16][64];
    __shared__ float Bs[2][16][64];
    int tid = threadIdx.x;
    int tx = tid & 15, ty = tid >> 4;          // micro: rows ty*8..+7, cols tx*4..+3
    int r = tid & 63, half = tid >> 6;         // loader: row r, k-half
    int h8 = half * 8;
    const float* Ap = A + (size_t)blockIdx.z * aB + (size_t)(blockIdx.y * 64 + r) * lda + h8;
    const float* Bp = Bm + (size_t)blockIdx.z * bB + (size_t)(blockIdx.x * 64 + r) * ldb + h8;

    float4 a0 = *(const float4*)(Ap);
    float4 a1 = *(const float4*)(Ap + 4);
    float4 b0 = *(const float4*)(Bp);
    float4 b1 = *(const float4*)(Bp + 4);
    As[0][h8 + 0][r] = a0.x; As[0][h8 + 1][r] = a0.y; As[0][h8 + 2][r] = a0.z; As[0][h8 + 3][r] = a0.w;
    As[0][h8 + 4][r] = a1.x; As[0][h8 + 5][r] = a1.y; As[0][h8 + 6][r] = a1.z; As[0][h8 + 7][r] = a1.w;
    Bs[0][h8 + 0][r] = b0.x; Bs[0][h8 + 1][r] = b0.y; Bs[0][h8 + 2][r] = b0.z; Bs[0][h8 + 3][r] = b0.w;
    Bs[0][h8 + 4][r] = b1.x; Bs[0][h8 + 5][r] = b1.y; Bs[0][h8 + 6][r] = b1.z; Bs[0][h8 + 7][r] = b1.w;
    __syncthreads();

    float acc[8][4] = {};
    int nIt = K >> 4;
    for (int it = 0; it < nIt; ++it) {
        int buf = it & 1;
        bool more = (it + 1) < nIt;
        if (more) {
            int k0 = (it + 1) << 4;
            a0 = *(const float4*)(Ap + k0);
            a1 = *(const float4*)(Ap + k0 + 4);
            b0 = *(const float4*)(Bp + k0);
            b1 = *(const float4*)(Bp + k0 + 4);
        }
        #pragma unroll
        for (int kk = 0; kk < 16; kk++) {
            float a[8], b[4];
            *(float4*)&a[0] = *(const float4*)&As[buf][kk][ty * 8];
            *(float4*)&a[4] = *(const float4*)&As[buf][kk][ty * 8 + 4];
            *(float4*)&b[0] = *(const float4*)&Bs[buf][kk][tx * 4];
            #pragma unroll
            for (int i = 0; i < 8; i++)
                #pragma unroll
                for (int j = 0; j < 4; j++) acc[i][j] += a[i] * b[j];
        }
        if (more) {
            int nb = buf ^ 1;
            As[nb][h8 + 0][r] = a0.x; As[nb][h8 + 1][r] = a0.y; As[nb][h8 + 2][r] = a0.z; As[nb][h8 + 3][r] = a0.w;
            As[nb][h8 + 4][r] = a1.x; As[nb][h8 + 5][r] = a1.y; As[nb][h8 + 6][r] = a1.z; As[nb][h8 + 7][r] = a1.w;
            Bs[nb][h8 + 0][r] = b0.x; Bs[nb][h8 + 1][r] = b0.y; Bs[nb][h8 + 2][r] = b0.z; Bs[nb][h8 + 3][r] = b0.w;
            Bs[nb][h8 + 4][r] = b1.x; Bs[nb][h8 + 5][r] = b1.y; Bs[nb][h8 + 6][r] = b1.z; Bs[nb][h8 + 7][r] = b1.w;
            __syncthreads();
        }
    }

    int row0 = blockIdx.y * 64 + ty * 8;
    int col0 = blockIdx.x * 64 + tx * 4;
    if (MODE == 1) {
        float inm[4];
        #pragma unroll
        for (int j = 0; j < 4; j++) inm[j] = 1.f / g_mem_norm[col0 + j];
        #pragma unroll
        for (int i = 0; i < 8; i++) {
            float ins = 1.f / g_src_norm[row0 + i];
            float mx = -1e30f;
            #pragma unroll
            for (int j = 0; j < 4; j++) mx = fmaxf(mx, acc[i][j] * ins * inm[j]);
            #pragma unroll
            for (int o = 8; o; o >>= 1) mx = fmaxf(mx, __shfl_xor_sync(0xFFFFFFFFu, mx, o));
            if (tx == 0) g_blockmax[blockIdx.x * B_ + row0 + i] = mx;
        }
    } else {
        float bj[4];
        #pragma unroll
        for (int j = 0; j < 4; j++) bj[j] = bias ? bias[col0 + j] : 0.f;
        float* Cb = C + (size_t)blockIdx.z * cB;
        #pragma unroll
        for (int i = 0; i < 8; i++) {
            float v[4];
            #pragma unroll
            for (int j = 0; j < 4; j++) {
                v[j] = acc[i][j] + bj[j];
                if (MODE == 2) v[j] = fmaxf(v[j], 0.f);
            }
            *(float4*)&Cb[(size_t)(row0 + i) * ldc + col0] = make_float4(v[0], v[1], v[2], v[3]);
        }
    }
}

// ---------------- softmax over [M logits + self], normalized in place --------
__global__ void softmax_kernel(float* __restrict__ logits, const float* __restrict__ projsrc,
                               float* __restrict__ pself) {
    int h = blockIdx.x >> 8, b = blockIdx.x & 255;
    int tid = threadIdx.x, w = tid >> 5, lane = tid & 31;
    float* row = logits + ((size_t)(h * B_ + b)) * M_;

    __shared__ float s_ls, smax[8], ssum[8];
    if (tid < 32) {
        float q = projsrc[b * 768 + h * 32 + tid];
        float k = projsrc[b * 768 + 256 + h * 32 + tid];
        float d = q * k;
        #pragma unroll
        for (int o = 16; o; o >>= 1) d += __shfl_xor_sync(0xFFFFFFFFu, d, o);
        if (tid == 0) s_ls = d * SCALE_;
    }
    float4 v0 = ((const float4*)row)[tid * 2];
    float4 v1 = ((const float4*)row)[tid * 2 + 1];
    float x[8] = {v0.x, v0.y, v0.z, v0.w, v1.x, v1.y, v1.z, v1.w};
    float lmax = -1e30f;
    #pragma unroll
    for (int j = 0; j < 8; j++) { x[j] *= SCALE_; lmax = fmaxf(lmax, x[j]); }
    #pragma unroll
    for (int o = 16; o; o >>= 1) lmax = fmaxf(lmax, __shfl_xor_sync(0xFFFFFFFFu, lmax, o));
    if (lane == 0) smax[w] = lmax;
    __syncthreads();
    float gmax = s_ls;
    #pragma unroll
    for (int i = 0; i < 8; i++) gmax = fmaxf(gmax, smax[i]);
    float lsum = 0.f;
    #pragma unroll
    for (int j = 0; j < 8; j++) { x[j] = __expf(x[j] - gmax); lsum += x[j]; }
    #pragma unroll
    for (int o = 16; o; o >>= 1) lsum += __shfl_xor_sync(0xFFFFFFFFu, lsum, o);
    if (lane == 0) ssum[w] = lsum;
    __syncthreads();
    float eself = __expf(s_ls - gmax);
    float tot = eself;
    #pragma unroll
    for (int i = 0; i < 8; i++) tot += ssum[i];
    float inv = 1.f / tot;
    #pragma unroll
    for (int j = 0; j < 8; j++) x[j] *= inv;
    ((float4*)row)[tid * 2]     = make_float4(x[0], x[1], x[2], x[3]);
    ((float4*)row)[tid * 2 + 1] = make_float4(x[4], x[5], x[6], x[7]);
    if (tid == 0) pself[h * B_ + b] = eself * inv;
}

// ---------------- AV split-K: tile 128 rows x 32 cols, 128 thr, 8x4 micro ----
__global__ void __launch_bounds__(128)
av_kernel(const float* __restrict__ probs, const float* __restrict__ kv,
          float* __restrict__ part) {
    __shared__ float Ps[2][16][128];
    __shared__ float Vs[2][16][32];
    int tid = threadIdx.x;
    int tx = tid & 7, ty = tid >> 3;               // rows ty*8..+7, cols tx*4..+3
    int qb = blockIdx.x, split = blockIdx.y, h = blockIdx.z;

    const float* Prow = probs + ((size_t)(h * B_ + qb * 128 + tid)) * M_ + split * KSPLIT_;
    int vr = tid >> 3, vc = (tid & 7) * 4;
    const float* Vp = kv + (size_t)(split * KSPLIT_ + vr) * 512 + 256 + h * 32 + vc;

    float4 p0, p1, p2, p3, vv;
    p0 = *(const float4*)(Prow);     p1 = *(const float4*)(Prow + 4);
    p2 = *(const float4*)(Prow + 8); p3 = *(const float4*)(Prow + 12);
    vv = *(const float4*)(Vp);
    {
        Ps[0][0][tid]=p0.x; Ps[0][1][tid]=p0.y; Ps[0][2][tid]=p0.z; Ps[0][3][tid]=p0.w;
        Ps[0][4][tid]=p1.x; Ps[0][5][tid]=p1.y; Ps[0][6][tid]=p1.z; Ps[0][7][tid]=p1.w;
        Ps[0][8][tid]=p2.x; Ps[0][9][tid]=p2.y; Ps[0][10][tid]=p2.z; Ps[0][11][tid]=p2.w;
        Ps[0][12][tid]=p3.x; Ps[0][13][tid]=p3.y; Ps[0][14][tid]=p3.z; Ps[0][15][tid]=p3.w;
        *(float4*)&Vs[0][vr][vc] = vv;
    }
    __syncthreads();

    float acc[8][4] = {};
    const int nIt = KSPLIT_ / 16;   // 16
    for (int it = 0; it < nIt; ++it) {
        int buf = it & 1;
        bool more = (it + 1) < nIt;
        if (more) {
            int k0 = (it + 1) * 16;
            p0 = *(const float4*)(Prow + k0);      p1 = *(const float4*)(Prow + k0 + 4);
            p2 = *(const float4*)(Prow + k0 + 8);  p3 = *(const float4*)(Prow + k0 + 12);
            vv = *(const float4*)(Vp + (size_t)k0 * 512);
        }
        #pragma unroll
        for (int kk = 0; kk < 16; kk++) {
            float a[8], b[4];
            *(float4*)&a[0] = *(const float4*)&Ps[buf][kk][ty * 8];
            *(float4*)&a[4] = *(const float4*)&Ps[buf][kk][ty * 8 + 4];
            *(float4*)&b[0] = *(const float4*)&Vs[buf][kk][tx * 4];
            #pragma unroll
            for (int i = 0; i < 8; i++)
                #pragma unroll
                for (int j = 0; j < 4; j++) acc[i][j] += a[i] * b[j];
        }
        if (more) {
            int nb = buf ^ 1;
            Ps[nb][0][tid]=p0.x; Ps[nb][1][tid]=p0.y; Ps[nb][2][tid]=p0.z; Ps[nb][3][tid]=p0.w;
            Ps[nb][4][tid]=p1.x; Ps[nb][5][tid]=p1.y; Ps[nb][6][tid]=p1.z; Ps[nb][7][tid]=p1.w;
            Ps[nb][8][tid]=p2.x; Ps[nb][9][tid]=p2.y; Ps[nb][10][tid]=p2.z; Ps[nb][11][tid]=p2.w;
            Ps[nb][12][tid]=p3.x; Ps[nb][13][tid]=p3.y; Ps[nb][14][tid]=p3.z; Ps[nb][15][tid]=p3.w;
            *(float4*)&Vs[nb][vr][vc] = vv;
            __syncthreads();
        }
    }
    #pragma unroll
    for (int i = 0; i < 8; i++) {
        *(float4*)&part[(size_t)split * (B_ * D_) +
                        (size_t)(qb * 128 + ty * 8 + i) * D_ + h * 32 + tx * 4]
            = make_float4(acc[i][0], acc[i][1], acc[i][2], acc[i][3]);
    }
}

// ---------------- reduce AV partials + self term -> ctx ----------------------
__global__ void reduce_ctx_kernel(const float* __restrict__ part, const float* __restrict__ pself,
                                  const float* __restrict__ projsrc, float* __restrict__ ctx) {
    int b = blockIdx.x, d = threadIdx.x;
    int h = d >> 5;
    float s = 0.f;
    #pragma unroll
    for (int sp = 0; sp < NSPLIT_; sp++) s += part[(size_t)sp * (B_ * D_) + b * D_ + d];
    s += pself[h * B_ + b] * projsrc[b * 768 + 512 + d];
    ctx[b * D_ + d] = s;
}

// ---------------- LN with fused split-K reduce: out = LN(a + sum part + bias) -
__global__ void ln_split_kernel(const float* __restrict__ a, const float* __restrict__ part,
                                int nsplit, const float* __restrict__ bias,
                                const float* __restrict__ g, const float* __restrict__ be,
                                float* __restrict__ out) {
    int w = threadIdx.x >> 5, lane = threadIdx.x & 31;
    int row = blockIdx.x * 8 + w;
    size_t base = (size_t)row * D_ + lane * 8;
    float4 a0 = *(const float4*)(a + base);
    float4 a1 = *(const float4*)(a + base + 4);
    float x[8] = {a0.x, a0.y, a0.z, a0.w, a1.x, a1.y, a1.z, a1.w};
    for (int z = 0; z < nsplit; z++) {
        const float* pp = part + (size_t)z * (B_ * D_) + base;
        float4 p0 = *(const float4*)pp;
        float4 p1 = *(const float4*)(pp + 4);
        x[0]+=p0.x; x[1]+=p0.y; x[2]+=p0.z; x[3]+=p0.w;
        x[4]+=p1.x; x[5]+=p1.y; x[6]+=p1.z; x[7]+=p1.w;
    }
    float4 bb0 = *(const float4*)(bias + lane * 8);
    float4 bb1 = *(const float4*)(bias + lane * 8 + 4);
    x[0]+=bb0.x; x[1]+=bb0.y; x[2]+=bb0.z; x[3]+=bb0.w;
    x[4]+=bb1.x; x[5]+=bb1.y; x[6]+=bb1.z; x[7]+=bb1.w;

    float s = 0.f;
    #pragma unroll
    for (int j = 0; j < 8; j++) s += x[j];
    #pragma unroll
    for (int o = 16; o; o >>= 1) s += __shfl_xor_sync(0xFFFFFFFFu, s, o);
    float mean = s * (1.f / D_);
    float v = 0.f;
    #pragma unroll
    for (int j = 0; j < 8; j++) { float c = x[j] - mean; v += c * c; }
    #pragma unroll
    for (int o = 16; o; o >>= 1) v += __shfl_xor_sync(0xFFFFFFFFu, v, o);
    float rstd = rsqrtf(v * (1.f / D_) + 1e-5f);
    float4 g0 = *(const float4*)(g + lane * 8);
    float4 g1 = *(const float4*)(g + lane * 8 + 4);
    float4 e0 = *(const float4*)(be + lane * 8);
    float4 e1 = *(const float4*)(be + lane * 8 + 4);
    float gg[8] = {g0.x, g0.y, g0.z, g0.w, g1.x, g1.y, g1.z, g1.w};
    float ee[8] = {e0.x, e0.y, e0.z, e0.w, e1.x, e1.y, e1.z, e1.w};
    float o8[8];
    #pragma unroll
    for (int j = 0; j < 8; j++) o8[j] = (x[j] - mean) * rstd * gg[j] + ee[j];
    *(float4*)(out + base)     = make_float4(o8[0], o8[1], o8[2], o8[3]);
    *(float4*)(out + base + 4) = make_float4(o8[4], o8[5], o8[6], o8[7]);
}

// ---------------- scatter prep: surprises, accept prefix, inverse row map ----
__global__ void scatter_prep_kernel(const int* __restrict__ ptrp) {
    __shared__ int conds[256];
    __shared__ int pref[256];
    __shared__ float red[256];
    int t = threadIdx.x;
    // flag: any nonzero memory element
    float f = 0.f;
    #pragma unroll
    for (int j = 0; j < 8; j++) f += g_mem_sq[t + j * 256];
    red[t] = f; __syncthreads();
    #pragma unroll
    for (int o = 128; o; o >>= 1) { if (t < o) red[t] += red[t + o]; __syncthreads(); }
    int flag = red[0] > 0.f;
    // surprise from blockmax
    float mx = -1e30f;
    #pragma unroll
    for (int bn = 0; bn < 32; bn++) mx = fmaxf(mx, g_blockmax[bn * B_ + t]);
    float s = flag ? (1.0f - mx) : 1.0f;
    int ptr = *ptrp;
    long long forced = (long long)M_ - (long long)ptr;
    int cond = (s > THR_) || ((long long)t < forced);
    conds[t] = cond;
    // clear inverse map
    #pragma unroll
    for (int j = 0; j < 8; j++) g_row_src[t + j * 256] = -1;
    __syncthreads();
    if (t == 0) {
        int r = 0;
        for (int i = 0; i < 256; i++) { pref[i] = r; r += conds[i]; }
    }
    __syncthreads();
    g_upd_s[t] = s;
    if (cond) {
        long long p = (long long)ptr + pref[t];
        int idx = (int)(p % M_); if (idx < 0) idx += M_;
        g_row_src[idx] = t;
    }
}

// ---------------- full-coverage memory update (copy + scatter fused) ---------
__global__ void update_kernel(const float* __restrict__ mem, const float* __restrict__ mom,
                              const float* __restrict__ scores,
                              float* __restrict__ out_mem, float* __restrict__ out_mom,
                              float* __restrict__ out_sc) {
    int row = blockIdx.x, t = threadIdx.x;
    int i = g_row_src[row];
    size_t o = (size_t)row * D_ + t;
    float mval = mem[o], mo = mom[o];
    if (i >= 0) {
        float diff = g_h[i * D_ + t] - mval;
        float nm = MOM_ * mo + (1.0f - MOM_) * diff;
        out_mem[o] = mval + LR_ * nm;
        out_mom[o] = nm;
    } else {
        out_mem[o] = mval;
        out_mom[o] = mo;
    }
    if (t == 0) out_sc[row] = (i >= 0) ? g_upd_s[i] : scores[row];
}

// ---------------- launch -----------------------------------------------------
extern "C" void kernel_launch(void* const* d_in, const int* in_sizes, int n_in,
                              void* d_out, int out_size) {
    const float* src       = (const float*)d_in[0];
    const float* memory    = (const float*)d_in[1];
    const float* momentum  = (const float*)d_in[2];
    const float* scores    = (const float*)d_in[3];
    const float* in_proj_w = (const float*)d_in[4];
    const float* in_proj_b = (const float*)d_in[5];
    const float* out_w     = (const float*)d_in[6];
    const float* out_b     = (const float*)d_in[7];
    const float* w1        = (const float*)d_in[8];
    const float* b1        = (const float*)d_in[9];
    const float* w2        = (const float*)d_in[10];
    const float* b2        = (const float*)d_in[11];
    const float* g1        = (const float*)d_in[12];
    const float* be1       = (const float*)d_in[13];
    const float* g2        = (const float*)d_in[14];
    const float* be2       = (const float*)d_in[15];
    const int*   ptr       = (const int*)d_in[16];

    float* out     = (float*)d_out;
    float* out_mem = out + B_ * D_;
    float* out_mom = out_mem + M_ * D_;
    float* out_sc  = out_mom + M_ * D_;

    float *proj_p, *kv_p, *log_p, *pself_p, *part_p, *ap_p, *fp_p, *ctx_p, *h_p, *hid_p;
    cudaGetSymbolAddress((void**)&proj_p,  g_proj_src);
    cudaGetSymbolAddress((void**)&kv_p,    g_kv_mem);
    cudaGetSymbolAddress((void**)&log_p,   g_logits);
    cudaGetSymbolAddress((void**)&pself_p, g_pself);
    cudaGetSymbolAddress((void**)&part_p,  g_ctx_part);
    cudaGetSymbolAddress((void**)&ap_p,    g_attn_part);
    cudaGetSymbolAddress((void**)&fp_p,    g_ff_part);
    cudaGetSymbolAddress((void**)&ctx_p,   g_ctx);
    cudaGetSymbolAddress((void**)&h_p,     g_h);
    cudaGetSymbolAddress((void**)&hid_p,   g_hidden);

    norms_kernel<<<(B_ + M_ + 7) / 8, dim3(32, 8)>>>(src, memory);

    // src projections [256,768]
    sgemm128<0><<<dim3(12, 4, 1), 128>>>(src, in_proj_w, in_proj_b, proj_p,
                                         256, 256, 256, 768, 0, 0, 0);
    // memory k|v [2048,512]
    sgemm128<0><<<dim3(8, 32, 1), 128>>>(memory, in_proj_w + D_ * D_, in_proj_b + D_, kv_p,
                                         256, 256, 256, 512, 0, 0, 0);
    // surprise: cosine blockmax
    sgemm128<1><<<dim3(32, 4, 1), 128>>>(src, memory, nullptr, nullptr,
                                         256, 256, 256, 0, 0, 0, 0);
    // attention logits per head: q_h[256,32] @ k_h[2048,32]^T
    sgemm128<0><<<dim3(32, 4, H_), 128>>>(proj_p, kv_p, nullptr, log_p,
                                          32, 768, 512, 2048, 32, 32, B_ * M_);
    softmax_kernel<<<H_ * B_, 256>>>(log_p, proj_p, pself_p);
    av_kernel<<<dim3(2, NSPLIT_, H_), 128>>>(log_p, kv_p, part_p);
    reduce_ctx_kernel<<<B_, 256>>>(part_p, pself_p, proj_p, ctx_p);

    // out-proj split-K x4 -> partials; LN1 fuses reduce + bias
    sgemm128<0><<<dim3(4, 4, 4), 128>>>(ctx_p, out_w, nullptr, ap_p,
                                        64, 256, 256, 256, 64, 64, B_ * D_);
    ln_split_kernel<<<B_ / 8, 256>>>(src, ap_p, 4, out_b, g1, be1, h_p);

    // memory update
    scatter_prep_kernel<<<1, 256>>>(ptr);
    update_kernel<<<M_, 256>>>(memory, momentum, scores, out_mem, out_mom, out_sc);

    // FFN1 (full-K, relu+bias), FFN2 split-K x8 -> partials; LN2 fuses reduce
    sgemm128<2><<<dim3(16, 4, 1), 128>>>(h_p, w1, b1, hid_p,
                                         256, 256, 256, 1024, 0, 0, 0);
    sgemm128<0><<<dim3(4, 4, 8), 128>>>(hid_p, w2, nullptr, fp_p,
                                        128, 1024, 1024, 256, 128, 128, B_ * D_);
    ln_split_kernel<<<B_ / 8, 256>>>(h_p, fp_p, 8, b2, g2, be2, out);
}

// round 4
// speedup vs baseline: 3.4691x; 1.3919x over previous
#include <cuda_runtime.h>
#include <math.h>

#define B_   256
#define D_   256
#define H_   8
#define HD_  32
#define FF_  1024
#define M_   2048
#define SCALE_ 0.17677669529663687f   /* 1/sqrt(32) */
#define THR_ 0.5f
#define MOM_ 0.9f
#define LR_  0.1f
#define NSPLIT_ 16
#define KSPLIT_ (M_ / NSPLIT_)   /* 128 keys per split */

// ---------------- scratch (device globals) -----------------------------------
__device__ float g_proj_src[B_ * 3 * D_];        // [B,768] q|k|v of src
__device__ float g_kv_mem[M_ * 2 * D_];          // [M,512] k|v of memory
__device__ float g_logits[H_ * B_ * M_];         // [H][B][M] logits -> probs
__device__ float g_pself[H_ * B_];
__device__ float g_ctx_part[NSPLIT_ * B_ * D_];  // AV split-K partials
__device__ float g_attn_part[4 * B_ * D_];       // out-proj split-K partials
__device__ float g_ff_part[8 * B_ * D_];         // FFN2 split-K partials
__device__ float g_blockmax[32 * B_];            // cosine per-(bn,row) maxima
__device__ float g_src_norm[B_];
__device__ float g_mem_norm[M_];
__device__ float g_mem_sq[M_];
__device__ float g_ctx[B_ * D_];
__device__ float g_h[B_ * D_];
__device__ float g_hidden[B_ * FF_];
__device__ int   g_row_src[M_];                  // mem row -> update source (or -1)
__device__ float g_upd_s[B_];

// ---------------- row norms --------------------------------------------------
__global__ void norms_kernel(const float* __restrict__ src, const float* __restrict__ mem) {
    int row = blockIdx.x * 8 + threadIdx.y;
    int lane = threadIdx.x;
    if (row >= B_ + M_) return;
    bool is_src = row < B_;
    const float* base = is_src ? (src + row * D_) : (mem + (row - B_) * D_);
    float s = 0.f;
    #pragma unroll
    for (int d = lane; d < D_; d += 32) { float v = base[d]; s += v * v; }
    #pragma unroll
    for (int o = 16; o; o >>= 1) s += __shfl_xor_sync(0xFFFFFFFFu, s, o);
    if (lane == 0) {
        float nv = fmaxf(sqrtf(s), 1e-8f);
        if (is_src) g_src_norm[row] = nv;
        else { g_mem_norm[row - B_] = nv; g_mem_sq[row - B_] = s; }
    }
}

// ---------------- SGEMM: C[.,N] = A @ B^T, 64x64 tile, 128 thr, 8x4 micro ----
// Double-buffered smem, one __syncthreads per k-iter.
// MODE 0: (+bias) store. MODE 1: cosine blockmax epilogue. MODE 2: relu+bias.
// z-dim batching/split-K via element strides aB,bB,cB.
template <int MODE>
__global__ void __launch_bounds__(128)
sgemm128(const float* __restrict__ A, const float* __restrict__ Bm,
         const float* __restrict__ bias, float* __restrict__ C,
         int K, int lda, int ldb, int ldc, int aB, int bB, int cB) {
    __shared__ float As[2][16][64];
    __shared__ float Bs[2][16][64];
    int tid = threadIdx.x;
    int tx = tid & 15, ty = tid >> 4;          // micro: rows ty*8..+7, cols tx*4..+3
    int r = tid & 63, half = tid >> 6;         // loader: row r, k-half
    int h8 = half * 8;
    const float* Ap = A + (size_t)blockIdx.z * aB + (size_t)(blockIdx.y * 64 + r) * lda + h8;
    const float* Bp = Bm + (size_t)blockIdx.z * bB + (size_t)(blockIdx.x * 64 + r) * ldb + h8;

    float4 a0 = *(const float4*)(Ap);
    float4 a1 = *(const float4*)(Ap + 4);
    float4 b0 = *(const float4*)(Bp);
    float4 b1 = *(const float4*)(Bp + 4);
    As[0][h8 + 0][r] = a0.x; As[0][h8 + 1][r] = a0.y; As[0][h8 + 2][r] = a0.z; As[0][h8 + 3][r] = a0.w;
    As[0][h8 + 4][r] = a1.x; As[0][h8 + 5][r] = a1.y; As[0][h8 + 6][r] = a1.z; As[0][h8 + 7][r] = a1.w;
    Bs[0][h8 + 0][r] = b0.x; Bs[0][h8 + 1][r] = b0.y; Bs[0][h8 + 2][r] = b0.z; Bs[0][h8 + 3][r] = b0.w;
    Bs[0][h8 + 4][r] = b1.x; Bs[0][h8 + 5][r] = b1.y; Bs[0][h8 + 6][r] = b1.z; Bs[0][h8 + 7][r] = b1.w;
    __syncthreads();

    float acc[8][4] = {};
    int nIt = K >> 4;
    for (int it = 0; it < nIt; ++it) {
        int buf = it & 1;
        bool more = (it + 1) < nIt;
        if (more) {
            int k0 = (it + 1) << 4;
            a0 = *(const float4*)(Ap + k0);
            a1 = *(const float4*)(Ap + k0 + 4);
            b0 = *(const float4*)(Bp + k0);
            b1 = *(const float4*)(Bp + k0 + 4);
        }
        #pragma unroll
        for (int kk = 0; kk < 16; kk++) {
            float a[8], b[4];
            *(float4*)&a[0] = *(const float4*)&As[buf][kk][ty * 8];
            *(float4*)&a[4] = *(const float4*)&As[buf][kk][ty * 8 + 4];
            *(float4*)&b[0] = *(const float4*)&Bs[buf][kk][tx * 4];
            #pragma unroll
            for (int i = 0; i < 8; i++)
                #pragma unroll
                for (int j = 0; j < 4; j++) acc[i][j] += a[i] * b[j];
        }
        if (more) {
            int nb = buf ^ 1;
            As[nb][h8 + 0][r] = a0.x; As[nb][h8 + 1][r] = a0.y; As[nb][h8 + 2][r] = a0.z; As[nb][h8 + 3][r] = a0.w;
            As[nb][h8 + 4][r] = a1.x; As[nb][h8 + 5][r] = a1.y; As[nb][h8 + 6][r] = a1.z; As[nb][h8 + 7][r] = a1.w;
            Bs[nb][h8 + 0][r] = b0.x; Bs[nb][h8 + 1][r] = b0.y; Bs[nb][h8 + 2][r] = b0.z; Bs[nb][h8 + 3][r] = b0.w;
            Bs[nb][h8 + 4][r] = b1.x; Bs[nb][h8 + 5][r] = b1.y; Bs[nb][h8 + 6][r] = b1.z; Bs[nb][h8 + 7][r] = b1.w;
            __syncthreads();
        }
    }

    int row0 = blockIdx.y * 64 + ty * 8;
    int col0 = blockIdx.x * 64 + tx * 4;
    if (MODE == 1) {
        float inm[4];
        #pragma unroll
        for (int j = 0; j < 4; j++) inm[j] = 1.f / g_mem_norm[col0 + j];
        #pragma unroll
        for (int i = 0; i < 8; i++) {
            float ins = 1.f / g_src_norm[row0 + i];
            float mx = -1e30f;
            #pragma unroll
            for (int j = 0; j < 4; j++) mx = fmaxf(mx, acc[i][j] * ins * inm[j]);
            #pragma unroll
            for (int o = 8; o; o >>= 1) mx = fmaxf(mx, __shfl_xor_sync(0xFFFFFFFFu, mx, o));
            if (tx == 0) g_blockmax[blockIdx.x * B_ + row0 + i] = mx;
        }
    } else {
        float bj[4];
        #pragma unroll
        for (int j = 0; j < 4; j++) bj[j] = bias ? bias[col0 + j] : 0.f;
        float* Cb = C + (size_t)blockIdx.z * cB;
        #pragma unroll
        for (int i = 0; i < 8; i++) {
            float v[4];
            #pragma unroll
            for (int j = 0; j < 4; j++) {
                v[j] = acc[i][j] + bj[j];
                if (MODE == 2) v[j] = fmaxf(v[j], 0.f);
            }
            *(float4*)&Cb[(size_t)(row0 + i) * ldc + col0] = make_float4(v[0], v[1], v[2], v[3]);
        }
    }
}

// ---------------- softmax over [M logits + self], normalized in place --------
__global__ void softmax_kernel(float* __restrict__ logits, const float* __restrict__ projsrc,
                               float* __restrict__ pself) {
    int h = blockIdx.x >> 8, b = blockIdx.x & 255;
    int tid = threadIdx.x, w = tid >> 5, lane = tid & 31;
    float* row = logits + ((size_t)(h * B_ + b)) * M_;

    __shared__ float s_ls, smax[8], ssum[8];
    if (tid < 32) {
        float q = projsrc[b * 768 + h * 32 + tid];
        float k = projsrc[b * 768 + 256 + h * 32 + tid];
        float d = q * k;
        #pragma unroll
        for (int o = 16; o; o >>= 1) d += __shfl_xor_sync(0xFFFFFFFFu, d, o);
        if (tid == 0) s_ls = d * SCALE_;
    }
    float4 v0 = ((const float4*)row)[tid * 2];
    float4 v1 = ((const float4*)row)[tid * 2 + 1];
    float x[8] = {v0.x, v0.y, v0.z, v0.w, v1.x, v1.y, v1.z, v1.w};
    float lmax = -1e30f;
    #pragma unroll
    for (int j = 0; j < 8; j++) { x[j] *= SCALE_; lmax = fmaxf(lmax, x[j]); }
    #pragma unroll
    for (int o = 16; o; o >>= 1) lmax = fmaxf(lmax, __shfl_xor_sync(0xFFFFFFFFu, lmax, o));
    if (lane == 0) smax[w] = lmax;
    __syncthreads();
    float gmax = s_ls;
    #pragma unroll
    for (int i = 0; i < 8; i++) gmax = fmaxf(gmax, smax[i]);
    float lsum = 0.f;
    #pragma unroll
    for (int j = 0; j < 8; j++) { x[j] = __expf(x[j] - gmax); lsum += x[j]; }
    #pragma unroll
    for (int o = 16; o; o >>= 1) lsum += __shfl_xor_sync(0xFFFFFFFFu, lsum, o);
    if (lane == 0) ssum[w] = lsum;
    __syncthreads();
    float eself = __expf(s_ls - gmax);
    float tot = eself;
    #pragma unroll
    for (int i = 0; i < 8; i++) tot += ssum[i];
    float inv = 1.f / tot;
    #pragma unroll
    for (int j = 0; j < 8; j++) x[j] *= inv;
    ((float4*)row)[tid * 2]     = make_float4(x[0], x[1], x[2], x[3]);
    ((float4*)row)[tid * 2 + 1] = make_float4(x[4], x[5], x[6], x[7]);
    if (tid == 0) pself[h * B_ + b] = eself * inv;
}

// ---------------- AV split-K: tile 128 rows x 32 cols, 128 thr, 8x4 micro ----
__global__ void __launch_bounds__(128)
av_kernel(const float* __restrict__ probs, const float* __restrict__ kv,
          float* __restrict__ part) {
    __shared__ float Ps[2][16][128];
    __shared__ float Vs[2][16][32];
    int tid = threadIdx.x;
    int tx = tid & 7, ty = tid >> 3;               // rows ty*8..+7, cols tx*4..+3
    int qb = blockIdx.x, split = blockIdx.y, h = blockIdx.z;

    const float* Prow = probs + ((size_t)(h * B_ + qb * 128 + tid)) * M_ + split * KSPLIT_;
    int vr = tid >> 3, vc = (tid & 7) * 4;
    const float* Vp = kv + (size_t)(split * KSPLIT_ + vr) * 512 + 256 + h * 32 + vc;

    float4 p0, p1, p2, p3, vv;
    p0 = *(const float4*)(Prow);     p1 = *(const float4*)(Prow + 4);
    p2 = *(const float4*)(Prow + 8); p3 = *(const float4*)(Prow + 12);
    vv = *(const float4*)(Vp);
    {
        Ps[0][0][tid]=p0.x; Ps[0][1][tid]=p0.y; Ps[0][2][tid]=p0.z; Ps[0][3][tid]=p0.w;
        Ps[0][4][tid]=p1.x; Ps[0][5][tid]=p1.y; Ps[0][6][tid]=p1.z; Ps[0][7][tid]=p1.w;
        Ps[0][8][tid]=p2.x; Ps[0][9][tid]=p2.y; Ps[0][10][tid]=p2.z; Ps[0][11][tid]=p2.w;
        Ps[0][12][tid]=p3.x; Ps[0][13][tid]=p3.y; Ps[0][14][tid]=p3.z; Ps[0][15][tid]=p3.w;
        *(float4*)&Vs[0][vr][vc] = vv;
    }
    __syncthreads();

    float acc[8][4] = {};
    const int nIt = KSPLIT_ / 16;
    for (int it = 0; it < nIt; ++it) {
        int buf = it & 1;
        bool more = (it + 1) < nIt;
        if (more) {
            int k0 = (it + 1) * 16;
            p0 = *(const float4*)(Prow + k0);      p1 = *(const float4*)(Prow + k0 + 4);
            p2 = *(const float4*)(Prow + k0 + 8);  p3 = *(const float4*)(Prow + k0 + 12);
            vv = *(const float4*)(Vp + (size_t)k0 * 512);
        }
        #pragma unroll
        for (int kk = 0; kk < 16; kk++) {
            float a[8], b[4];
            *(float4*)&a[0] = *(const float4*)&Ps[buf][kk][ty * 8];
            *(float4*)&a[4] = *(const float4*)&Ps[buf][kk][ty * 8 + 4];
            *(float4*)&b[0] = *(const float4*)&Vs[buf][kk][tx * 4];
            #pragma unroll
            for (int i = 0; i < 8; i++)
                #pragma unroll
                for (int j = 0; j < 4; j++) acc[i][j] += a[i] * b[j];
        }
        if (more) {
            int nb = buf ^ 1;
            Ps[nb][0][tid]=p0.x; Ps[nb][1][tid]=p0.y; Ps[nb][2][tid]=p0.z; Ps[nb][3][tid]=p0.w;
            Ps[nb][4][tid]=p1.x; Ps[nb][5][tid]=p1.y; Ps[nb][6][tid]=p1.z; Ps[nb][7][tid]=p1.w;
            Ps[nb][8][tid]=p2.x; Ps[nb][9][tid]=p2.y; Ps[nb][10][tid]=p2.z; Ps[nb][11][tid]=p2.w;
            Ps[nb][12][tid]=p3.x; Ps[nb][13][tid]=p3.y; Ps[nb][14][tid]=p3.z; Ps[nb][15][tid]=p3.w;
            *(float4*)&Vs[nb][vr][vc] = vv;
            __syncthreads();
        }
    }
    #pragma unroll
    for (int i = 0; i < 8; i++) {
        *(float4*)&part[(size_t)split * (B_ * D_) +
                        (size_t)(qb * 128 + ty * 8 + i) * D_ + h * 32 + tx * 4]
            = make_float4(acc[i][0], acc[i][1], acc[i][2], acc[i][3]);
    }
}

// ---------------- reduce AV partials + self term -> ctx ----------------------
__global__ void reduce_ctx_kernel(const float* __restrict__ part, const float* __restrict__ pself,
                                  const float* __restrict__ projsrc, float* __restrict__ ctx) {
    int b = blockIdx.x, d = threadIdx.x;
    int h = d >> 5;
    float s = 0.f;
    #pragma unroll
    for (int sp = 0; sp < NSPLIT_; sp++) s += part[(size_t)sp * (B_ * D_) + b * D_ + d];
    s += pself[h * B_ + b] * projsrc[b * 768 + 512 + d];
    ctx[b * D_ + d] = s;
}

// ---------------- LN with fused split-K reduce: out = LN(a + sum part + bias) -
__global__ void ln_split_kernel(const float* __restrict__ a, const float* __restrict__ part,
                                int nsplit, const float* __restrict__ bias,
                                const float* __restrict__ g, const float* __restrict__ be,
                                float* __restrict__ out) {
    int w = threadIdx.x >> 5, lane = threadIdx.x & 31;
    int row = blockIdx.x * 8 + w;
    size_t base = (size_t)row * D_ + lane * 8;
    float4 a0 = *(const float4*)(a + base);
    float4 a1 = *(const float4*)(a + base + 4);
    float x[8] = {a0.x, a0.y, a0.z, a0.w, a1.x, a1.y, a1.z, a1.w};
    for (int z = 0; z < nsplit; z++) {
        const float* pp = part + (size_t)z * (B_ * D_) + base;
        float4 p0 = *(const float4*)pp;
        float4 p1 = *(const float4*)(pp + 4);
        x[0]+=p0.x; x[1]+=p0.y; x[2]+=p0.z; x[3]+=p0.w;
        x[4]+=p1.x; x[5]+=p1.y; x[6]+=p1.z; x[7]+=p1.w;
    }
    float4 bb0 = *(const float4*)(bias + lane * 8);
    float4 bb1 = *(const float4*)(bias + lane * 8 + 4);
    x[0]+=bb0.x; x[1]+=bb0.y; x[2]+=bb0.z; x[3]+=bb0.w;
    x[4]+=bb1.x; x[5]+=bb1.y; x[6]+=bb1.z; x[7]+=bb1.w;

    float s = 0.f;
    #pragma unroll
    for (int j = 0; j < 8; j++) s += x[j];
    #pragma unroll
    for (int o = 16; o; o >>= 1) s += __shfl_xor_sync(0xFFFFFFFFu, s, o);
    float mean = s * (1.f / D_);
    float v = 0.f;
    #pragma unroll
    for (int j = 0; j < 8; j++) { float c = x[j] - mean; v += c * c; }
    #pragma unroll
    for (int o = 16; o; o >>= 1) v += __shfl_xor_sync(0xFFFFFFFFu, v, o);
    float rstd = rsqrtf(v * (1.f / D_) + 1e-5f);
    float4 g0 = *(const float4*)(g + lane * 8);
    float4 g1 = *(const float4*)(g + lane * 8 + 4);
    float4 e0 = *(const float4*)(be + lane * 8);
    float4 e1 = *(const float4*)(be + lane * 8 + 4);
    float gg[8] = {g0.x, g0.y, g0.z, g0.w, g1.x, g1.y, g1.z, g1.w};
    float ee[8] = {e0.x, e0.y, e0.z, e0.w, e1.x, e1.y, e1.z, e1.w};
    float o8[8];
    #pragma unroll
    for (int j = 0; j < 8; j++) o8[j] = (x[j] - mean) * rstd * gg[j] + ee[j];
    *(float4*)(out + base)     = make_float4(o8[0], o8[1], o8[2], o8[3]);
    *(float4*)(out + base + 4) = make_float4(o8[4], o8[5], o8[6], o8[7]);
}

// ---------------- scatter prep: surprises, accept prefix, inverse row map ----
__global__ void scatter_prep_kernel(const int* __restrict__ ptrp) {
    __shared__ int conds[256];
    __shared__ int pref[256];
    __shared__ float red[256];
    int t = threadIdx.x;
    float f = 0.f;
    #pragma unroll
    for (int j = 0; j < 8; j++) f += g_mem_sq[t + j * 256];
    red[t] = f; __syncthreads();
    #pragma unroll
    for (int o = 128; o; o >>= 1) { if (t < o) red[t] += red[t + o]; __syncthreads(); }
    int flag = red[0] > 0.f;
    float mx = -1e30f;
    #pragma unroll
    for (int bn = 0; bn < 32; bn++) mx = fmaxf(mx, g_blockmax[bn * B_ + t]);
    float s = flag ? (1.0f - mx) : 1.0f;
    int ptr = *ptrp;
    long long forced = (long long)M_ - (long long)ptr;
    int cond = (s > THR_) || ((long long)t < forced);
    conds[t] = cond;
    #pragma unroll
    for (int j = 0; j < 8; j++) g_row_src[t + j * 256] = -1;
    __syncthreads();
    if (t == 0) {
        int r = 0;
        for (int i = 0; i < 256; i++) { pref[i] = r; r += conds[i]; }
    }
    __syncthreads();
    g_upd_s[t] = s;
    if (cond) {
        long long p = (long long)ptr + pref[t];
        int idx = (int)(p % M_); if (idx < 0) idx += M_;
        g_row_src[idx] = t;
    }
}

// ---------------- full-coverage memory update (copy + scatter fused) ---------
__global__ void update_kernel(const float* __restrict__ mem, const float* __restrict__ mom,
                              const float* __restrict__ scores,
                              float* __restrict__ out_mem, float* __restrict__ out_mom,
                              float* __restrict__ out_sc) {
    int row = blockIdx.x, t = threadIdx.x;
    int i = g_row_src[row];
    size_t o = (size_t)row * D_ + t;
    float mval = mem[o], mo = mom[o];
    if (i >= 0) {
        float diff = g_h[i * D_ + t] - mval;
        float nm = MOM_ * mo + (1.0f - MOM_) * diff;
        out_mem[o] = mval + LR_ * nm;
        out_mom[o] = nm;
    } else {
        out_mem[o] = mval;
        out_mom[o] = mo;
    }
    if (t == 0) out_sc[row] = (i >= 0) ? g_upd_s[i] : scores[row];
}

// ---------------- launch -----------------------------------------------------
extern "C" void kernel_launch(void* const* d_in, const int* in_sizes, int n_in,
                              void* d_out, int out_size) {
    const float* src       = (const float*)d_in[0];
    const float* memory    = (const float*)d_in[1];
    const float* momentum  = (const float*)d_in[2];
    const float* scores    = (const float*)d_in[3];
    const float* in_proj_w = (const float*)d_in[4];
    const float* in_proj_b = (const float*)d_in[5];
    const float* out_w     = (const float*)d_in[6];
    const float* out_b     = (const float*)d_in[7];
    const float* w1        = (const float*)d_in[8];
    const float* b1        = (const float*)d_in[9];
    const float* w2        = (const float*)d_in[10];
    const float* b2        = (const float*)d_in[11];
    const float* g1        = (const float*)d_in[12];
    const float* be1       = (const float*)d_in[13];
    const float* g2        = (const float*)d_in[14];
    const float* be2       = (const float*)d_in[15];
    const int*   ptr       = (const int*)d_in[16];

    float* out     = (float*)d_out;
    float* out_mem = out + B_ * D_;
    float* out_mom = out_mem + M_ * D_;
    float* out_sc  = out_mom + M_ * D_;

    float *proj_p, *kv_p, *log_p, *pself_p, *part_p, *ap_p, *fp_p, *ctx_p, *h_p, *hid_p;
    cudaGetSymbolAddress((void**)&proj_p,  g_proj_src);
    cudaGetSymbolAddress((void**)&kv_p,    g_kv_mem);
    cudaGetSymbolAddress((void**)&log_p,   g_logits);
    cudaGetSymbolAddress((void**)&pself_p, g_pself);
    cudaGetSymbolAddress((void**)&part_p,  g_ctx_part);
    cudaGetSymbolAddress((void**)&ap_p,    g_attn_part);
    cudaGetSymbolAddress((void**)&fp_p,    g_ff_part);
    cudaGetSymbolAddress((void**)&ctx_p,   g_ctx);
    cudaGetSymbolAddress((void**)&h_p,     g_h);
    cudaGetSymbolAddress((void**)&hid_p,   g_hidden);

    // persistent side streams/events (host objects, created once; graph edges via events)
    static cudaStream_t s1 = nullptr, s2 = nullptr;
    static cudaEvent_t eFork = nullptr, eKV = nullptr, eS2 = nullptr, eLN1 = nullptr, eUpd = nullptr;
    if (!s1) {
        cudaStreamCreateWithFlags(&s1, cudaStreamNonBlocking);
        cudaStreamCreateWithFlags(&s2, cudaStreamNonBlocking);
        cudaEventCreateWithFlags(&eFork, cudaEventDisableTiming);
        cudaEventCreateWithFlags(&eKV,   cudaEventDisableTiming);
        cudaEventCreateWithFlags(&eS2,   cudaEventDisableTiming);
        cudaEventCreateWithFlags(&eLN1,  cudaEventDisableTiming);
        cudaEventCreateWithFlags(&eUpd,  cudaEventDisableTiming);
    }

    // ---- fork ----
    cudaEventRecord(eFork, 0);
    cudaStreamWaitEvent(s1, eFork, 0);
    cudaStreamWaitEvent(s2, eFork, 0);

    // S1: memory k|v projection [2048,512]
    sgemm128<0><<<dim3(8, 32, 1), 128, 0, s1>>>(memory, in_proj_w + D_ * D_, in_proj_b + D_, kv_p,
                                                256, 256, 256, 512, 0, 0, 0);
    cudaEventRecord(eKV, s1);

    // S2: norms -> cosine blockmax -> scatter prep (independent of attention chain)
    norms_kernel<<<(B_ + M_ + 7) / 8, dim3(32, 8), 0, s2>>>(src, memory);
    sgemm128<1><<<dim3(32, 4, 1), 128, 0, s2>>>(src, memory, nullptr, nullptr,
                                                256, 256, 256, 0, 0, 0, 0);
    scatter_prep_kernel<<<1, 256, 0, s2>>>(ptr);
    cudaEventRecord(eS2, s2);

    // S0: src projections [256,768]
    sgemm128<0><<<dim3(12, 4, 1), 128>>>(src, in_proj_w, in_proj_b, proj_p,
                                         256, 256, 256, 768, 0, 0, 0);

    // S0 waits for KV, then attention chain
    cudaStreamWaitEvent(0, eKV, 0);
    sgemm128<0><<<dim3(32, 4, H_), 128>>>(proj_p, kv_p, nullptr, log_p,
                                          32, 768, 512, 2048, 32, 32, B_ * M_);
    softmax_kernel<<<H_ * B_, 256>>>(log_p, proj_p, pself_p);
    av_kernel<<<dim3(2, NSPLIT_, H_), 128>>>(log_p, kv_p, part_p);
    reduce_ctx_kernel<<<B_, 256>>>(part_p, pself_p, proj_p, ctx_p);

    // out-proj split-K x4 -> partials; LN1 fuses reduce + bias
    sgemm128<0><<<dim3(4, 4, 4), 128>>>(ctx_p, out_w, nullptr, ap_p,
                                        64, 256, 256, 256, 64, 64, B_ * D_);
    ln_split_kernel<<<B_ / 8, 256>>>(src, ap_p, 4, out_b, g1, be1, h_p);
    cudaEventRecord(eLN1, 0);

    // S1: memory update path (needs h from LN1 + scatter map from S2), overlaps FFN
    cudaStreamWaitEvent(s1, eLN1, 0);
    cudaStreamWaitEvent(s1, eS2, 0);
    update_kernel<<<M_, 256, 0, s1>>>(memory, momentum, scores, out_mem, out_mom, out_sc);
    cudaEventRecord(eUpd, s1);

    // S0: FFN1 (full-K, relu+bias), FFN2 split-K x8 -> partials; LN2 fuses reduce
    sgemm128<2><<<dim3(16, 4, 1), 128>>>(h_p, w1, b1, hid_p,
                                         256, 256, 256, 1024, 0, 0, 0);
    sgemm128<0><<<dim3(4, 4, 8), 128>>>(hid_p, w2, nullptr, fp_p,
                                        128, 1024, 1024, 256, 128, 128, B_ * D_);
    ln_split_kernel<<<B_ / 8, 256>>>(h_p, fp_p, 8, b2, g2, be2, out);

    // ---- join ----
    cudaStreamWaitEvent(0, eUpd, 0);
}